// round 5
// baseline (speedup 1.0000x reference)
#include <cuda_runtime.h>
#include <cuda_bf16.h>
#include <math.h>

#define D     128
#define MAX_N 50048
#define MAX_E 800000

// ---- scratch: __device__ globals, device-side references only ----
__device__ float g_buf1[MAX_N * D];     // GEMM outputs h
__device__ float g_buf2[MAX_N * D];     // layer-1 activations
__device__ float g_dinv[MAX_N];
__device__ int   g_deg[MAX_N];
__device__ int   g_rowptr[MAX_N + 1];
__device__ int   g_cursor[MAX_N];
__device__ int   g_csr_src[MAX_E];
__device__ float g_csr_w[MAX_E];
__device__ int   g_bsum[512];
__device__ int   g_is32;                // 1 => edge_index is int32

// ================= edge dtype probe =================
// int64 node ids (<50000, little-endian): every odd int32 word is 0.
// int32 data: odd words are random node ids (P[all 2048 zero] ~ 0).
__global__ void detect_dtype_kernel(const int* __restrict__ ei32) {
    __shared__ int sh;
    if (threadIdx.x == 0) sh = 0;
    __syncthreads();
    int nz = 0;
    for (int i = threadIdx.x; i < 2048; i += 256)
        nz |= ei32[2 * i + 1];
    if (nz) atomicOr(&sh, 1);
    __syncthreads();
    if (threadIdx.x == 0) g_is32 = sh;
}

__device__ __forceinline__ int edge_at(const void* ei, int idx) {
    return g_is32 ? ((const int*)ei)[idx]
                  : (int)((const long long*)ei)[idx];
}

// ================= degree / norm =================
__global__ void deg_zero_kernel(int n) {
    int i = blockIdx.x * blockDim.x + threadIdx.x;
    if (i < n) g_deg[i] = 0;
}

__global__ void deg_count_kernel(const void* __restrict__ ei, int E) {
    int e = blockIdx.x * blockDim.x + threadIdx.x;
    if (e < E) atomicAdd(&g_deg[edge_at(ei, E + e)], 1);
}

__global__ void dinv_kernel(int n) {
    int i = blockIdx.x * blockDim.x + threadIdx.x;
    if (i < n) g_dinv[i] = rsqrtf((float)(g_deg[i] + 1));   // +1 self-loop
}

// ================= exclusive scan over deg (3 kernels) =================
__global__ void scan_bsums_kernel(int n) {
    __shared__ int sh[256];
    int i = blockIdx.x * 256 + threadIdx.x;
    sh[threadIdx.x] = (i < n) ? g_deg[i] : 0;
    __syncthreads();
    for (int s = 128; s; s >>= 1) {
        if (threadIdx.x < s) sh[threadIdx.x] += sh[threadIdx.x + s];
        __syncthreads();
    }
    if (threadIdx.x == 0) g_bsum[blockIdx.x] = sh[0];
}

__global__ void scan_bsum_scan_kernel(int nb) {   // single block, 256 threads
    __shared__ int sh[256];
    int tid = threadIdx.x;
    int v = (tid < nb) ? g_bsum[tid] : 0;
    sh[tid] = v;
    __syncthreads();
    for (int off = 1; off < 256; off <<= 1) {
        int t = (tid >= off) ? sh[tid - off] : 0;
        __syncthreads();
        sh[tid] += t;
        __syncthreads();
    }
    g_bsum[tid] = sh[tid] - v;   // exclusive
}

__global__ void scan_final_kernel(int n) {
    __shared__ int wsum[8];
    int i = blockIdx.x * 256 + threadIdx.x;
    int lane = threadIdx.x & 31, wid = threadIdx.x >> 5;
    int v = (i < n) ? g_deg[i] : 0;
    int x = v;
#pragma unroll
    for (int o = 1; o < 32; o <<= 1) {
        int t = __shfl_up_sync(0xffffffffu, x, o);
        if (lane >= o) x += t;
    }
    if (lane == 31) wsum[wid] = x;
    __syncthreads();
    if (threadIdx.x == 0) {
        int s = 0;
        for (int j = 0; j < 8; j++) { int t = wsum[j]; wsum[j] = s; s += t; }
    }
    __syncthreads();
    int excl = x - v + wsum[wid] + g_bsum[blockIdx.x];
    if (i < n) {
        g_rowptr[i] = excl;
        g_cursor[i] = excl;
        if (i == n - 1) g_rowptr[n] = excl + v;
    }
}

// ================= CSR bucket fill =================
__global__ void csr_fill_kernel(const void* __restrict__ ei, int E) {
    int e = blockIdx.x * blockDim.x + threadIdx.x;
    if (e >= E) return;
    int s = edge_at(ei, e);
    int d = edge_at(ei, E + e);
    int pos = atomicAdd(&g_cursor[d], 1);
    g_csr_src[pos] = s;
    g_csr_w[pos] = g_dinv[s] * g_dinv[d];
}

// ================= GEMM: g_buf1[n,128] = A[n,128] @ W[128,128] =================
// A_in == nullptr -> read from g_buf2 (layer 2).
__global__ __launch_bounds__(256, 2) void gemm_kernel(
    const float* __restrict__ A_in, const float* __restrict__ W, int n)
{
    const float* A = A_in ? A_in : g_buf2;
    __shared__ float As[16][132];
    __shared__ float Bs[16][128];
    const int tid = threadIdx.x;
    const int tx = tid & 15;
    const int ty = tid >> 4;
    const int rowBase = blockIdx.x * 128;

    float acc[8][8];
#pragma unroll
    for (int r = 0; r < 8; r++)
#pragma unroll
        for (int c = 0; c < 8; c++) acc[r][c] = 0.f;

    for (int kc = 0; kc < D; kc += 16) {
#pragma unroll
        for (int i = tid; i < 128 * 16; i += 256) {
            int r = i >> 4, k = i & 15;
            int row = rowBase + r;
            As[k][r] = (row < n) ? A[(size_t)row * D + kc + k] : 0.f;
        }
#pragma unroll
        for (int i = tid; i < 16 * 128; i += 256) {
            int k = i >> 7, c = i & 127;
            Bs[k][c] = W[(size_t)(kc + k) * D + c];
        }
        __syncthreads();
#pragma unroll
        for (int k = 0; k < 16; k++) {
            float a[8], b[8];
#pragma unroll
            for (int r = 0; r < 8; r++) a[r] = As[k][ty * 8 + r];
#pragma unroll
            for (int c = 0; c < 8; c++) b[c] = Bs[k][tx + 16 * c];
#pragma unroll
            for (int r = 0; r < 8; r++)
#pragma unroll
                for (int c = 0; c < 8; c++)
                    acc[r][c] += a[r] * b[c];
        }
        __syncthreads();
    }
#pragma unroll
    for (int r = 0; r < 8; r++) {
        int row = rowBase + ty * 8 + r;
        if (row < n) {
#pragma unroll
            for (int c = 0; c < 8; c++)
                g_buf1[(size_t)row * D + tx + 16 * c] = acc[r][c];
        }
    }
}

// ================= gather aggregation (warp per dst row) =================
__device__ __forceinline__ float4 agg_row(int row, int lane)
{
    const float4* h4 = (const float4*)g_buf1;
    float di = g_dinv[row];
    float w0 = di * di;
    float4 acc = h4[row * 32 + lane];
    acc.x *= w0; acc.y *= w0; acc.z *= w0; acc.w *= w0;

    int end = g_rowptr[row + 1];
    int e = g_rowptr[row];
    for (; e + 1 < end; e += 2) {
        int s0 = g_csr_src[e], s1 = g_csr_src[e + 1];
        float we0 = g_csr_w[e], we1 = g_csr_w[e + 1];
        float4 v0 = h4[s0 * 32 + lane];
        float4 v1 = h4[s1 * 32 + lane];
        acc.x += v0.x * we0 + v1.x * we1;
        acc.y += v0.y * we0 + v1.y * we1;
        acc.z += v0.z * we0 + v1.z * we1;
        acc.w += v0.w * we0 + v1.w * we1;
    }
    if (e < end) {
        int s0 = g_csr_src[e];
        float we = g_csr_w[e];
        float4 v0 = h4[s0 * 32 + lane];
        acc.x += v0.x * we; acc.y += v0.y * we;
        acc.z += v0.z * we; acc.w += v0.w * we;
    }
    return acc;
}

// layer-1 epilogue: g_buf2 = relu(agg + b1)
__global__ void agg_bias_relu_kernel(const float* __restrict__ b, int n)
{
    int gt = blockIdx.x * blockDim.x + threadIdx.x;
    int row = gt >> 5, lane = gt & 31;
    if (row >= n) return;
    float4 acc = agg_row(row, lane);
    float4 bb = ((const float4*)b)[lane];
    acc.x = fmaxf(acc.x + bb.x, 0.f);
    acc.y = fmaxf(acc.y + bb.y, 0.f);
    acc.z = fmaxf(acc.z + bb.z, 0.f);
    acc.w = fmaxf(acc.w + bb.w, 0.f);
    ((float4*)g_buf2)[row * 32 + lane] = acc;
}

// layer-2 epilogue + linear head: out = sigmoid((agg+b2)@Wl + bl)
__global__ void agg_head_kernel(const float* __restrict__ b2,
                                const float* __restrict__ Wl,
                                const float* __restrict__ bl,
                                float* __restrict__ out, int n)
{
    int gt = blockIdx.x * blockDim.x + threadIdx.x;
    int row = gt >> 5, lane = gt & 31;
    if (row >= n) return;
    float4 acc = agg_row(row, lane);
    float4 bb = ((const float4*)b2)[lane];
    float4 wv = ((const float4*)Wl)[lane];
    float s = (acc.x + bb.x) * wv.x + (acc.y + bb.y) * wv.y
            + (acc.z + bb.z) * wv.z + (acc.w + bb.w) * wv.w;
#pragma unroll
    for (int o = 16; o; o >>= 1) s += __shfl_xor_sync(0xffffffffu, s, o);
    if (lane == 0) out[row] = 1.f / (1.f + expf(-(s + bl[0])));
}

// ================= host =================
extern "C" void kernel_launch(void* const* d_in, const int* in_sizes, int n_in,
                              void* d_out, int out_size)
{
    const float* x  = (const float*)d_in[0];
    const void*  ei = d_in[1];                  // int32 or int64, probed on device
    const float* W1 = (const float*)d_in[2];
    const float* b1 = (const float*)d_in[3];
    const float* W2 = (const float*)d_in[4];
    const float* b2 = (const float*)d_in[5];
    const float* Wl = (const float*)d_in[6];
    const float* bl = (const float*)d_in[7];
    float* out = (float*)d_out;

    const int n = in_sizes[0] / D;   // 50000
    const int E = in_sizes[1] / 2;   // 800000 (element count is dtype-independent)

    const int TB = 256;
    int nb_n     = (n + TB - 1) / TB;
    int nb_E     = (E + TB - 1) / TB;
    int nb_warpN = (n * 32 + TB - 1) / TB;
    int nb_gemm  = (n + 127) / 128;

    // dtype probe + degrees + dinv + CSR
    detect_dtype_kernel<<<1, TB>>>((const int*)ei);
    deg_zero_kernel<<<nb_n, TB>>>(n);
    deg_count_kernel<<<nb_E, TB>>>(ei, E);
    dinv_kernel<<<nb_n, TB>>>(n);
    scan_bsums_kernel<<<nb_n, TB>>>(n);
    scan_bsum_scan_kernel<<<1, TB>>>(nb_n);
    scan_final_kernel<<<nb_n, TB>>>(n);
    csr_fill_kernel<<<nb_E, TB>>>(ei, E);

    // layer 1: h1 = x@W1 -> g_buf1 ; agg+bias+relu -> g_buf2
    gemm_kernel<<<nb_gemm, TB>>>(x, W1, n);
    agg_bias_relu_kernel<<<nb_warpN, TB>>>(b1, n);

    // layer 2: h2 = g_buf2@W2 -> g_buf1 ; agg+bias+head -> out
    gemm_kernel<<<nb_gemm, TB>>>(nullptr, W2, n);
    agg_head_kernel<<<nb_warpN, TB>>>(b2, Wl, bl, out, n);
}